// round 2
// baseline (speedup 1.0000x reference)
#include <cuda_runtime.h>
#include <cstdint>
#include <cstddef>

// LSTM: T=512, B=64, I=512, H=512, fp32.
// Phase 1: x_proj[t][g][b] = sum_i x[t,b,i]*W_ih[g,i] + b_ih[g] + b_hh[g]   (GEMM, parallel)
// Phase 2: persistent recurrent kernel, 128 blocks, flag-barrier per step.

#define TT   512
#define BB   64
#define II   512
#define HH   512
#define GG   2048   // 4*H

typedef unsigned long long ull;

// ---------------- device scratch (no cudaMalloc allowed) ----------------
__device__ float    g_xproj[(size_t)TT * GG * BB];   // 256 MB, [t][g][b]
__device__ float    g_hbuf[2][HH * BB];              // [k][b] layout, double buffered
__device__ unsigned g_flags[128];                    // per-block step flags (monotonic)

// ---------------- helpers ----------------
__device__ __forceinline__ ull fma2(ull a, ull b, ull c) {
    ull d;
    asm("fma.rn.f32x2 %0, %1, %2, %3;" : "=l"(d) : "l"(a), "l"(b), "l"(c));
    return d;
}
__device__ __forceinline__ ull pack2(float x, float y) {
    ull d;
    asm("mov.b64 %0, {%1, %2};" : "=l"(d) : "f"(x), "f"(y));
    return d;
}
__device__ __forceinline__ float2 unpack2(ull v) {
    float2 r;
    asm("mov.b64 {%0, %1}, %2;" : "=f"(r.x), "=f"(r.y) : "l"(v));
    return r;
}
__device__ __forceinline__ unsigned ld_acq(const unsigned* p) {
    unsigned v;
    asm volatile("ld.global.acquire.gpu.u32 %0, [%1];" : "=r"(v) : "l"(p));
    return v;
}
__device__ __forceinline__ void st_rel(unsigned* p, unsigned v) {
    asm volatile("st.global.release.gpu.u32 [%0], %1;" :: "l"(p), "r"(v));
}
__device__ __forceinline__ float sigm(float x) {
    return 1.0f / (1.0f + __expf(-x));
}

// ---------------- Phase 1: input projection GEMM ----------------
// Block tile: 128 g  x  64 b (one t per block). K=512, k-tile 16.
// Microtile per thread: 8g x 4b, f32x2 packed over g-pairs.
__global__ void __launch_bounds__(256) xproj_kernel(
    const float* __restrict__ x,     // [T][B][I]
    const float* __restrict__ Wih,   // [G][I]
    const float* __restrict__ bih,   // [G]
    const float* __restrict__ bhh)   // [G]
{
    __shared__ float As[16][128];   // [k][g]
    __shared__ float Bs[16][64];    // [k][b]

    const int t    = blockIdx.y;
    const int gblk = blockIdx.x * 128;
    const int tid  = threadIdx.x;
    const int ty   = tid >> 4;        // 0..15
    const int tx   = tid & 15;        // 0..15
    const int g0   = ty * 8;
    const int b0   = tx * 4;

    // global load mapping
    const int ag = tid >> 1;            // 0..127  (g row)
    const int ah = (tid & 1) * 8;       // k sub-offset
    const float* Aptr = Wih + (size_t)(gblk + ag) * II + ah;
    const int bb = tid >> 2;            // 0..63   (b row)
    const int bq = (tid & 3) * 4;       // k sub-offset
    const float* Bptr = x + (size_t)t * (BB * II) + (size_t)bb * II + bq;

    ull acc[4][4];
#pragma unroll
    for (int i = 0; i < 4; ++i)
#pragma unroll
        for (int j = 0; j < 4; ++j) acc[i][j] = 0ull;

    float4 pa0 = *(const float4*)(Aptr);
    float4 pa1 = *(const float4*)(Aptr + 4);
    float4 pb  = *(const float4*)(Bptr);

    for (int kt = 0; kt < 32; ++kt) {
        As[ah + 0][ag] = pa0.x; As[ah + 1][ag] = pa0.y;
        As[ah + 2][ag] = pa0.z; As[ah + 3][ag] = pa0.w;
        As[ah + 4][ag] = pa1.x; As[ah + 5][ag] = pa1.y;
        As[ah + 6][ag] = pa1.z; As[ah + 7][ag] = pa1.w;
        Bs[bq + 0][bb] = pb.x;  Bs[bq + 1][bb] = pb.y;
        Bs[bq + 2][bb] = pb.z;  Bs[bq + 3][bb] = pb.w;
        __syncthreads();

        if (kt < 31) {
            pa0 = *(const float4*)(Aptr + (kt + 1) * 16);
            pa1 = *(const float4*)(Aptr + (kt + 1) * 16 + 4);
            pb  = *(const float4*)(Bptr + (kt + 1) * 16);
        }

#pragma unroll
        for (int kk = 0; kk < 16; ++kk) {
            ulonglong2 a01 = *(const ulonglong2*)&As[kk][g0];
            ulonglong2 a23 = *(const ulonglong2*)&As[kk][g0 + 4];
            float4 bv = *(const float4*)&Bs[kk][b0];
            ull bd0 = pack2(bv.x, bv.x);
            ull bd1 = pack2(bv.y, bv.y);
            ull bd2 = pack2(bv.z, bv.z);
            ull bd3 = pack2(bv.w, bv.w);
            acc[0][0] = fma2(a01.x, bd0, acc[0][0]);
            acc[0][1] = fma2(a01.x, bd1, acc[0][1]);
            acc[0][2] = fma2(a01.x, bd2, acc[0][2]);
            acc[0][3] = fma2(a01.x, bd3, acc[0][3]);
            acc[1][0] = fma2(a01.y, bd0, acc[1][0]);
            acc[1][1] = fma2(a01.y, bd1, acc[1][1]);
            acc[1][2] = fma2(a01.y, bd2, acc[1][2]);
            acc[1][3] = fma2(a01.y, bd3, acc[1][3]);
            acc[2][0] = fma2(a23.x, bd0, acc[2][0]);
            acc[2][1] = fma2(a23.x, bd1, acc[2][1]);
            acc[2][2] = fma2(a23.x, bd2, acc[2][2]);
            acc[2][3] = fma2(a23.x, bd3, acc[2][3]);
            acc[3][0] = fma2(a23.y, bd0, acc[3][0]);
            acc[3][1] = fma2(a23.y, bd1, acc[3][1]);
            acc[3][2] = fma2(a23.y, bd2, acc[3][2]);
            acc[3][3] = fma2(a23.y, bd3, acc[3][3]);
        }
        __syncthreads();
    }

    // epilogue: add bias, store [t][g][b]
    float* Ct = g_xproj + (size_t)t * (GG * BB);
#pragma unroll
    for (int gp = 0; gp < 4; ++gp) {
        int g = gblk + g0 + gp * 2;
        float bias0 = bih[g] + bhh[g];
        float bias1 = bih[g + 1] + bhh[g + 1];
#pragma unroll
        for (int b = 0; b < 4; ++b) {
            float2 v = unpack2(acc[gp][b]);
            Ct[(size_t)g * BB + (b0 + b)]       = v.x + bias0;
            Ct[(size_t)(g + 1) * BB + (b0 + b)] = v.y + bias1;
        }
    }
}

// ---------------- Phase 2: persistent recurrent kernel ----------------
// 128 blocks x 128 threads. Block owns 4 h-columns => 16 W_hh rows in SMEM.
// h stored [k][b] so batch pairs are contiguous for f32x2.
#define REC_SMEM_FLOATS (8192 /*Ws*/ + 8192 /*hs*/ + 1024 /*gates*/ + 256 /*cs*/)

__global__ void __launch_bounds__(128) lstm_rec_kernel(
    const float* __restrict__ Whh,   // [G][H]
    float* __restrict__ out)         // [T][B][H]
{
    extern __shared__ float sm[];
    float* Ws     = sm;              // [512][16]  (transposed: rows contiguous per k)
    float* hs     = sm + 8192;       // [128][64]  (one k-tile of h)
    float* gate_s = sm + 16384;      // [16][64]
    float* cs     = sm + 17408;      // [4][64]

    const int tid = threadIdx.x;
    const int bid = blockIdx.x;
    const int j0  = bid * 4;

    // load W_hh slice, transposed to Ws[k][r]
    {
        int r = tid >> 3, seg = tid & 7;
        int q = r >> 2, jj = r & 3;
        const float* wrow = Whh + (size_t)(q * HH + j0 + jj) * HH + seg * 64;
#pragma unroll
        for (int i = 0; i < 64; i += 4) {
            float4 v = *(const float4*)(wrow + i);
            int k = seg * 64 + i;
            Ws[(k + 0) * 16 + r] = v.x;
            Ws[(k + 1) * 16 + r] = v.y;
            Ws[(k + 2) * 16 + r] = v.z;
            Ws[(k + 3) * 16 + r] = v.w;
        }
    }
    cs[tid] = 0.0f;
    cs[tid + 128] = 0.0f;

    __shared__ unsigned s_base;
    if (tid == 0) s_base = ld_acq(&g_flags[bid]);
    __syncthreads();
    const unsigned base = s_base;

    const int rp = tid >> 4;       // 0..7  -> rows r0=rp*2, r0+1
    const int r0 = rp * 2;
    const int b4 = (tid & 15) * 4; // 4 batches -> 2 f32x2 pairs

    const int jjA = tid >> 6;      // epilogue: elems (jjA,be) and (jjA+2,be)
    const int be  = tid & 63;

    for (int t = 0; t < TT; ++t) {
        // prefetch x_proj for this step's epilogue (independent of flags)
        float xp[2][4];
        {
            const float* xpt = g_xproj + (size_t)t * (GG * BB);
#pragma unroll
            for (int q = 0; q < 4; ++q) {
                xp[0][q] = __ldcs(xpt + (size_t)(q * HH + j0 + jjA) * BB + be);
                xp[1][q] = __ldcs(xpt + (size_t)(q * HH + j0 + jjA + 2) * BB + be);
            }
        }

        ull acc0 = 0, acc1 = 0, acc2 = 0, acc3 = 0;
        if (t > 0) {
            // flat flag barrier: wait until every block published h for step t-1
            if (tid < 32) {
                unsigned tgt = base + (unsigned)t;
                for (;;) {
                    unsigned v0 = ld_acq(&g_flags[tid]);
                    unsigned v1 = ld_acq(&g_flags[tid + 32]);
                    unsigned v2 = ld_acq(&g_flags[tid + 64]);
                    unsigned v3 = ld_acq(&g_flags[tid + 96]);
                    bool ok = ((int)(v0 - tgt) >= 0) & ((int)(v1 - tgt) >= 0) &
                              ((int)(v2 - tgt) >= 0) & ((int)(v3 - tgt) >= 0);
                    if (__all_sync(0xffffffffu, ok)) break;
                    __nanosleep(64);   // back off: avoid hammering L2 with flag polls
                }
            }
            __syncthreads();

            const float4* hsrc = (const float4*)(g_hbuf[(t + 1) & 1]); // buf written at t-1
            float4 pre[16];
#pragma unroll
            for (int i = 0; i < 16; ++i)
                pre[i] = __ldcg(hsrc + tid + i * 128);

            for (int kt = 0; kt < 4; ++kt) {
#pragma unroll
                for (int i = 0; i < 16; ++i)
                    ((float4*)hs)[tid + i * 128] = pre[i];
                __syncthreads();
                if (kt < 3) {
#pragma unroll
                    for (int i = 0; i < 16; ++i)
                        pre[i] = __ldcg(hsrc + (kt + 1) * 2048 + tid + i * 128);
                }
#pragma unroll 8
                for (int k = 0; k < 128; ++k) {
                    int ka = kt * 128 + k;
                    float2 wv = *(const float2*)&Ws[ka * 16 + r0];
                    ull wd0 = pack2(wv.x, wv.x);
                    ull wd1 = pack2(wv.y, wv.y);
                    ulonglong2 hp = *(const ulonglong2*)&hs[k * 64 + b4];
                    acc0 = fma2(hp.x, wd0, acc0);
                    acc1 = fma2(hp.y, wd0, acc1);
                    acc2 = fma2(hp.x, wd1, acc2);
                    acc3 = fma2(hp.y, wd1, acc3);
                }
                __syncthreads();
            }
        }

        // scatter gate partials to SMEM
        {
            float2 v;
            v = unpack2(acc0); gate_s[r0 * 64 + b4 + 0] = v.x; gate_s[r0 * 64 + b4 + 1] = v.y;
            v = unpack2(acc1); gate_s[r0 * 64 + b4 + 2] = v.x; gate_s[r0 * 64 + b4 + 3] = v.y;
            v = unpack2(acc2); gate_s[(r0 + 1) * 64 + b4 + 0] = v.x; gate_s[(r0 + 1) * 64 + b4 + 1] = v.y;
            v = unpack2(acc3); gate_s[(r0 + 1) * 64 + b4 + 2] = v.x; gate_s[(r0 + 1) * 64 + b4 + 3] = v.y;
        }
        __syncthreads();

        // gate math + state update, 2 elements per thread
        float* hdst = g_hbuf[t & 1];
#pragma unroll
        for (int e = 0; e < 2; ++e) {
            int jj = jjA + e * 2;
            float gi = gate_s[(0 * 4 + jj) * 64 + be] + xp[e][0];
            float gf = gate_s[(1 * 4 + jj) * 64 + be] + xp[e][1];
            float gg = gate_s[(2 * 4 + jj) * 64 + be] + xp[e][2];
            float go = gate_s[(3 * 4 + jj) * 64 + be] + xp[e][3];
            float iv = sigm(gi);
            float fv = sigm(gf);
            float gv = tanhf(gg);
            float ov = sigm(go);
            float c = fv * cs[jj * 64 + be] + iv * gv;
            cs[jj * 64 + be] = c;
            float h = ov * tanhf(c);
            out[(size_t)t * (BB * HH) + (size_t)be * HH + j0 + jj] = h;
            __stcg(&hdst[(j0 + jj) * 64 + be], h);
        }
        __threadfence();
        __syncthreads();
        if (tid == 0) st_rel(&g_flags[bid], base + (unsigned)t + 1u);
    }
}

// ---------------- launch ----------------
extern "C" void kernel_launch(void* const* d_in, const int* in_sizes, int n_in,
                              void* d_out, int out_size)
{
    const float* x   = (const float*)d_in[0];
    const float* Wih = (const float*)d_in[1];
    const float* Whh = (const float*)d_in[2];
    const float* bih = (const float*)d_in[3];
    const float* bhh = (const float*)d_in[4];
    float* out = (float*)d_out;

    dim3 g1(GG / 128, TT);
    xproj_kernel<<<g1, 256>>>(x, Wih, bih, bhh);

    size_t smem = (size_t)REC_SMEM_FLOATS * sizeof(float);
    cudaFuncSetAttribute(lstm_rec_kernel,
                         cudaFuncAttributeMaxDynamicSharedMemorySize, (int)smem);
    lstm_rec_kernel<<<128, 128, smem>>>(Whh, out);
}

// round 5
// speedup vs baseline: 1.0259x; 1.0259x over previous
#include <cuda_runtime.h>
#include <cstdint>
#include <cstddef>

// Fused LSTM: T=512, B=64, I=512, H=512, fp32.
// Kernel 1: transpose x -> xT[t][i][b]
// Kernel 2: persistent fused kernel, 128 blocks x 256 threads.
//   warps 0-3: h-GEMM (recurrent, flag-gated)   warps 4-7: x-GEMM (independent)

#define TT   512
#define BB   64
#define HH   512

typedef unsigned long long ull;

__device__ float    g_xT[(size_t)TT * HH * BB];      // 64 MB, [t][i][b]
__device__ float    g_hbuf[2][HH * BB];              // [k][b], double buffered
__device__ unsigned g_flags[128];                    // monotonic per-block step flags

// ---------------- helpers ----------------
__device__ __forceinline__ ull fma2(ull a, ull b, ull c) {
    ull d;
    asm("fma.rn.f32x2 %0, %1, %2, %3;" : "=l"(d) : "l"(a), "l"(b), "l"(c));
    return d;
}
__device__ __forceinline__ float2 unpack2(ull v) {
    float2 r;
    asm("mov.b64 {%0, %1}, %2;" : "=f"(r.x), "=f"(r.y) : "l"(v));
    return r;
}
__device__ __forceinline__ unsigned ld_acq(const unsigned* p) {
    unsigned v;
    asm volatile("ld.global.acquire.gpu.u32 %0, [%1];" : "=r"(v) : "l"(p));
    return v;
}
__device__ __forceinline__ void st_rel(unsigned* p, unsigned v) {
    asm volatile("st.global.release.gpu.u32 [%0], %1;" :: "l"(p), "r"(v));
}
__device__ __forceinline__ void barx(int id) {  // named barrier, 128 threads
    asm volatile("bar.sync %0, 128;" :: "r"(id) : "memory");
}
__device__ __forceinline__ float sigm(float x) {
    return 1.0f / (1.0f + __expf(-x));
}

// ---------------- Kernel 1: x transpose to [t][i][b] ----------------
__global__ void __launch_bounds__(256) xT_kernel(const float* __restrict__ x)
{
    __shared__ float ts[64][65];
    const int t  = blockIdx.y;
    const int i0 = blockIdx.x * 64;
    const int tid = threadIdx.x;
#pragma unroll
    for (int p = 0; p < 16; ++p) {
        int lin = p * 256 + tid;
        int b = lin >> 6, i = lin & 63;
        ts[i][b] = x[((size_t)t * BB + b) * HH + i0 + i];
    }
    __syncthreads();
#pragma unroll
    for (int p = 0; p < 16; ++p) {
        int lin = p * 256 + tid;
        int i = lin >> 6, b = lin & 63;
        g_xT[((size_t)t * HH + i0 + i) * BB + b] = ts[i][b];
    }
}

// ---------------- Kernel 2: fused persistent LSTM ----------------
// SMEM float offsets:
//   Wd     [512][16] float2 (w,w)   : 0      .. 16383
//   Xd     [512][16] float2         : 16384  .. 32767
//   hs     [128][64]                : 32768  .. 40959
//   xs     [128][64]                : 40960  .. 49151
//   gate_h [16][64]                 : 49152  .. 50175
//   gate_x [16][64]                 : 50176  .. 51199
//   hout   [4][64]                  : 51200  .. 51455
//   bias   [16]                     : 51456  .. 51471
#define SM_TOTAL_FLOATS 51472

__global__ void __launch_bounds__(256, 1) lstm_fused_kernel(
    const float* __restrict__ Wih,   // [4H][I]
    const float* __restrict__ Whh,   // [4H][H]
    const float* __restrict__ bih,
    const float* __restrict__ bhh,
    float* __restrict__ out)         // [T][B][H]
{
    extern __shared__ float sm[];
    float* Wd     = sm;
    float* Xd     = sm + 16384;
    float* hs     = sm + 32768;
    float* xs     = sm + 40960;
    float* gate_h = sm + 49152;
    float* gate_x = sm + 50176;
    float* hout   = sm + 51200;
    float* bias_s = sm + 51456;

    const int tid  = threadIdx.x;
    const int bid  = blockIdx.x;
    const int j0   = bid * 4;
    const int grp  = tid >> 7;        // 0 = h-group, 1 = x-group
    const int gtid = tid & 127;
    const int wg   = gtid >> 5;       // 0..3 within group
    const int lane = gtid & 31;

    // compute-tile mapping: warp covers 8 row-pairs x 32 batches
    const int r0 = (wg & 1) * 8 + ((lane >> 3) << 1);        // 0,2,..,14
    const int b4 = (wg >> 1) * 32 + ((lane & 7) << 2);       // 0,4,..,60

    // ---- init: load W slices duplicated (w,w), bias ----
    {
        int r = gtid >> 3, seg = gtid & 7;  // r 0..15, seg 0..7 (k-chunk of 64)
        int grow = (r >> 2) * HH + j0 + (r & 3);
        const float* src = (grp == 0 ? Whh : Wih) + (size_t)grow * HH + seg * 64;
        float2* dst = (float2*)(grp == 0 ? Wd : Xd);
#pragma unroll
        for (int q = 0; q < 64; q += 4) {
            float4 v = *(const float4*)(src + q);
            int k = seg * 64 + q;
            dst[(k + 0) * 16 + r] = make_float2(v.x, v.x);
            dst[(k + 1) * 16 + r] = make_float2(v.y, v.y);
            dst[(k + 2) * 16 + r] = make_float2(v.z, v.z);
            dst[(k + 3) * 16 + r] = make_float2(v.w, v.w);
        }
    }
    if (tid < 16) {
        int grow = (tid >> 2) * HH + j0 + (tid & 3);
        bias_s[tid] = bih[grow] + bhh[grow];
    }

    __shared__ unsigned s_base;
    if (tid == 0) s_base = ld_acq(&g_flags[bid]);
    __syncthreads();
    const unsigned base = s_base;

    // epilogue mapping + register cell state
    const int jj = (tid >> 6) & 3;
    const int be = tid & 63;
    float c_reg = 0.0f;

    for (int t = 0; t < TT; ++t) {
        ull a0 = 0, a1 = 0, a2 = 0, a3 = 0;

        if (grp == 0) {
            // ---------------- h-GEMM group ----------------
            if (t > 0) {
                if (wg == 0) {   // warp 0 polls all 128 flags
                    unsigned tgt = base + (unsigned)t;
                    for (;;) {
                        unsigned v0 = ld_acq(&g_flags[lane]);
                        unsigned v1 = ld_acq(&g_flags[lane + 32]);
                        unsigned v2 = ld_acq(&g_flags[lane + 64]);
                        unsigned v3 = ld_acq(&g_flags[lane + 96]);
                        bool ok = ((int)(v0 - tgt) >= 0) & ((int)(v1 - tgt) >= 0) &
                                  ((int)(v2 - tgt) >= 0) & ((int)(v3 - tgt) >= 0);
                        if (__all_sync(0xffffffffu, ok)) break;
                        __nanosleep(32);
                    }
                }
                barx(1);

                const float4* hsrc = (const float4*)(g_hbuf[(t + 1) & 1]);
                float4 pre[16];
#pragma unroll
                for (int i = 0; i < 16; ++i)
                    pre[i] = __ldcg(hsrc + gtid + i * 128);

                for (int kt = 0; kt < 4; ++kt) {
#pragma unroll
                    for (int i = 0; i < 16; ++i)
                        ((float4*)hs)[gtid + i * 128] = pre[i];
                    barx(1);
                    if (kt < 3) {
#pragma unroll
                        for (int i = 0; i < 16; ++i)
                            pre[i] = __ldcg(hsrc + (kt + 1) * 2048 + gtid + i * 128);
                    }
#pragma unroll 8
                    for (int k = 0; k < 128; ++k) {
                        ulonglong2 wp = *(const ulonglong2*)&Wd[((kt * 128 + k) * 16 + r0) * 2];
                        ulonglong2 hp = *(const ulonglong2*)&hs[k * 64 + b4];
                        a0 = fma2(hp.x, wp.x, a0);
                        a1 = fma2(hp.y, wp.x, a1);
                        a2 = fma2(hp.x, wp.y, a2);
                        a3 = fma2(hp.y, wp.y, a3);
                    }
                    barx(1);
                }
            }
            // scatter partials
            float2 v;
            v = unpack2(a0); gate_h[r0 * 64 + b4 + 0] = v.x; gate_h[r0 * 64 + b4 + 1] = v.y;
            v = unpack2(a1); gate_h[r0 * 64 + b4 + 2] = v.x; gate_h[r0 * 64 + b4 + 3] = v.y;
            v = unpack2(a2); gate_h[(r0 + 1) * 64 + b4 + 0] = v.x; gate_h[(r0 + 1) * 64 + b4 + 1] = v.y;
            v = unpack2(a3); gate_h[(r0 + 1) * 64 + b4 + 2] = v.x; gate_h[(r0 + 1) * 64 + b4 + 3] = v.y;
        } else {
            // ---------------- x-GEMM group ----------------
            const float4* xsrc = (const float4*)(g_xT + (size_t)t * (HH * BB));
            float4 pre[16];
#pragma unroll
            for (int i = 0; i < 16; ++i)
                pre[i] = __ldcs(xsrc + gtid + i * 128);

            for (int kt = 0; kt < 4; ++kt) {
#pragma unroll
                for (int i = 0; i < 16; ++i)
                    ((float4*)xs)[gtid + i * 128] = pre[i];
                barx(2);
                if (kt < 3) {
#pragma unroll
                    for (int i = 0; i < 16; ++i)
                        pre[i] = __ldcs(xsrc + (kt + 1) * 2048 + gtid + i * 128);
                }
#pragma unroll 8
                for (int k = 0; k < 128; ++k) {
                    ulonglong2 wp = *(const ulonglong2*)&Xd[((kt * 128 + k) * 16 + r0) * 2];
                    ulonglong2 hp = *(const ulonglong2*)&xs[k * 64 + b4];
                    a0 = fma2(hp.x, wp.x, a0);
                    a1 = fma2(hp.y, wp.x, a1);
                    a2 = fma2(hp.x, wp.y, a2);
                    a3 = fma2(hp.y, wp.y, a3);
                }
                barx(2);
            }
            float bz0 = bias_s[r0], bz1 = bias_s[r0 + 1];
            float2 v;
            v = unpack2(a0); gate_x[r0 * 64 + b4 + 0] = v.x + bz0; gate_x[r0 * 64 + b4 + 1] = v.y + bz0;
            v = unpack2(a1); gate_x[r0 * 64 + b4 + 2] = v.x + bz0; gate_x[r0 * 64 + b4 + 3] = v.y + bz0;
            v = unpack2(a2); gate_x[(r0 + 1) * 64 + b4 + 0] = v.x + bz1; gate_x[(r0 + 1) * 64 + b4 + 1] = v.y + bz1;
            v = unpack2(a3); gate_x[(r0 + 1) * 64 + b4 + 2] = v.x + bz1; gate_x[(r0 + 1) * 64 + b4 + 3] = v.y + bz1;
        }

        __syncthreads();

        // ---------------- gate epilogue (all 256 threads, 1 element each) ----
        {
            float gi = gate_h[(0 * 4 + jj) * 64 + be] + gate_x[(0 * 4 + jj) * 64 + be];
            float gf = gate_h[(1 * 4 + jj) * 64 + be] + gate_x[(1 * 4 + jj) * 64 + be];
            float gg = gate_h[(2 * 4 + jj) * 64 + be] + gate_x[(2 * 4 + jj) * 64 + be];
            float go = gate_h[(3 * 4 + jj) * 64 + be] + gate_x[(3 * 4 + jj) * 64 + be];
            float iv = sigm(gi);
            float fv = sigm(gf);
            float gv = tanhf(gg);
            float ov = sigm(go);
            c_reg = fv * c_reg + iv * gv;
            float h = ov * tanhf(c_reg);
            __stcg(&g_hbuf[t & 1][(j0 + jj) * 64 + be], h);
            hout[jj * 64 + be] = h;
        }
        __threadfence();
        __syncthreads();
        if (tid == 0) st_rel(&g_flags[bid], base + (unsigned)t + 1u);

        // coalesced out write: thread b < 64 writes float4 [t][b][j0..j0+3]
        if (tid < 64) {
            float4 hv = make_float4(hout[tid], hout[64 + tid], hout[128 + tid], hout[192 + tid]);
            *(float4*)&out[((size_t)t * BB + tid) * HH + j0] = hv;
        }
    }
}

// ---------------- launch ----------------
extern "C" void kernel_launch(void* const* d_in, const int* in_sizes, int n_in,
                              void* d_out, int out_size)
{
    const float* x   = (const float*)d_in[0];
    const float* Wih = (const float*)d_in[1];
    const float* Whh = (const float*)d_in[2];
    const float* bih = (const float*)d_in[3];
    const float* bhh = (const float*)d_in[4];
    float* out = (float*)d_out;

    dim3 gT(HH / 64, TT);
    xT_kernel<<<gT, 256>>>(x);

    size_t smem = (size_t)SM_TOTAL_FLOATS * sizeof(float);
    cudaFuncSetAttribute(lstm_fused_kernel,
                         cudaFuncAttributeMaxDynamicSharedMemorySize, (int)smem);
    lstm_fused_kernel<<<128, 256, smem>>>(Wih, Whh, bih, bhh, out);
}